// round 16
// baseline (speedup 1.0000x reference)
#include <cuda_runtime.h>

#define NBATCH   4096
#define TT       256
#define NSTEPS   255
#define ND       16
#define SD       8
#define HH       64
#define INX      24    // SD + ND
#define KIN      88    // INX + HH
#define G4       256
#define NB       32    // batch rows per CTA
#define XPAD     36    // xB row stride (floats), 144B (16B-aligned rows)
#define APAD     34    // a1T/a2 row stride (float2), 272B (16B-aligned rows)
#define NTHREADS 512

typedef unsigned long long u64;

struct __align__(16) Smem {
    float4 wz4[KIN][HH];      // (wi,wf,wg,wo) per (k, unit)
    float2 w1p[HH][HH];       // (wmu, wvar) per (k, out)
    float2 w2p[HH][HH];
    float2 w3p[HH][SD];
    float4 bz4[HH];
    float2 b1p[HH];
    float2 b2p[HH];
    float2 b3p[SD];
    float  xB[KIN][XPAD];     // rows: 0..7 x, 8..23 noise, 24..87 h ; col = belem
    float2 a1T[HH][APAD];     // k-major: a1T[out_of_L1][belem] = (mu, var)
    float2 a2T[HH][APAD];     // k-major: a2T[out_of_L2][belem] = (mu, var)
};

// ---- packed f32x2 helpers ----
__device__ __forceinline__ u64 pk2(float a, float b) {
    u64 r; asm("mov.b64 %0, {%1, %2};" : "=l"(r) : "f"(a), "f"(b)); return r;
}
__device__ __forceinline__ void upk2(u64 v, float& a, float& b) {
    asm("mov.b64 {%0, %1}, %2;" : "=f"(a), "=f"(b) : "l"(v));
}
__device__ __forceinline__ u64 fma2(u64 a, u64 b, u64 c) {
    u64 d; asm("fma.rn.f32x2 %0, %1, %2, %3;" : "=l"(d) : "l"(a), "l"(b), "l"(c)); return d;
}

__device__ __forceinline__ float sigm(float x) {
    return __fdividef(1.f, 1.f + __expf(-x));
}
__device__ __forceinline__ float ftanh(float x) {
    float a = fabsf(x);
    float e = __expf(2.f * a);
    float r = 1.f - __fdividef(2.f, e + 1.f);
    return copysignf(r, x);
}

__global__ __launch_bounds__(NTHREADS, 1)
void genlstm_kernel(
    const float* __restrict__ g_noise, const float* __restrict__ g_eps,
    const float* __restrict__ Wx, const float* __restrict__ Wh, const float* __restrict__ b_g,
    const float* __restrict__ Wm1, const float* __restrict__ bm1,
    const float* __restrict__ Wm2, const float* __restrict__ bm2,
    const float* __restrict__ Wm3, const float* __restrict__ bm3,
    const float* __restrict__ Wv1, const float* __restrict__ bv1,
    const float* __restrict__ Wv2, const float* __restrict__ bv2,
    const float* __restrict__ Wv3, const float* __restrict__ bv3,
    float* __restrict__ g_out)
{
    extern __shared__ float smraw[];
    Smem* sm = reinterpret_cast<Smem*>(smraw);
    const int tid = threadIdx.x;
    const int wid = tid >> 5;
    const int b0  = blockIdx.x * NB;

    // ================= one-time staging =================
    for (int i = tid; i < KIN * G4; i += NTHREADS) {
        int k = i >> 8, r = i & 255, uu = r >> 2, g = r & 3;
        float v = (k < INX) ? Wx[k * G4 + g * 64 + uu] : Wh[(k - INX) * G4 + g * 64 + uu];
        reinterpret_cast<float*>(sm->wz4)[k * 256 + uu * 4 + g] = v;
    }
    if (tid < HH) {
        sm->bz4[tid] = make_float4(b_g[tid], b_g[64 + tid], b_g[128 + tid], b_g[192 + tid]);
        sm->b1p[tid] = make_float2(bm1[tid], bv1[tid]);
        sm->b2p[tid] = make_float2(bm2[tid], bv2[tid]);
    }
    if (tid < SD) sm->b3p[tid] = make_float2(bm3[tid], bv3[tid]);
    for (int i = tid; i < HH * HH; i += NTHREADS) {
        int k = i >> 6, o = i & 63;
        sm->w1p[k][o] = make_float2(Wm1[i], Wv1[i]);
        sm->w2p[k][o] = make_float2(Wm2[i], Wv2[i]);
    }
    for (int i = tid; i < HH * SD; i += NTHREADS) {
        int k = i >> 3, d = i & 7;
        sm->w3p[k][d] = make_float2(Wm3[i], Wv3[i]);
    }
    for (int i = tid; i < KIN * XPAD; i += NTHREADS)
        reinterpret_cast<float*>(sm->xB)[i] = 0.f;
    __syncthreads();
    // stage noise(step 0)
    {
        int be = tid >> 4, nd = tid & 15;
        sm->xB[SD + nd][be] = g_noise[((size_t)(b0 + be) * NSTEPS) * ND + nd];
    }
    if (tid < 256) {   // out[:,0,:] = 0
        int be = tid >> 3, d = tid & 7;
        g_out[((size_t)(b0 + be) * TT) * SD + d] = 0.f;
    }
    __syncthreads();

    // ---- roles ----
    // warps 0-7 (tid<256): LSTM side — thread = (unit uA, 8-belem block gA)
    const int uA = tid & 63, gA = (tid >> 6) & 3;
    // warps 8-15 (tid>=256): MLP side
    const int g2 = tid - 256;               // 0..255
    const int oB = g2 & 63, gB = g2 >> 6;   // B/C: out unit, 8-belem block
    const int dD = g2 & 7,  beD = g2 >> 3;  // D/E: series dim, belem (0..31)

    // LSTM-side state
    u64 aIF[8], aGO[8];   // gate accumulators, carried across barriers
    float cst[8];         // cell state per (uA, 8 belems)
    float cum = 0.f;      // MLP side cumsum
    u64 bifR = 0, bgoR = 0;
    if (tid < 256) {
        float4 bz = sm->bz4[uA];
        bifR = pk2(bz.x, bz.y); bgoR = pk2(bz.z, bz.w);
#pragma unroll
        for (int j = 0; j < 8; j++) { aIF[j] = bifR; aGO[j] = bgoR; cst[j] = 0.f; }
    }

    for (int s = 0; s < NSTEPS; s++) {
        float epsv = 0.f;
        float2 nz = make_float2(0.f, 0.f);

        // ===== stage 1: zX + elementwise (warps 0-7) | prefetch (warps 8-15) =====
        if (tid < 256) {
#pragma unroll
            for (int k = 0; k < INX; k++) {
                float4 w = sm->wz4[k][uA];
                u64 wif = pk2(w.x, w.y), wgo = pk2(w.z, w.w);
                float4 x0 = *(const float4*)&sm->xB[k][gA * 8];
                float4 x1 = *(const float4*)&sm->xB[k][gA * 8 + 4];
                float xv[8] = {x0.x, x0.y, x0.z, x0.w, x1.x, x1.y, x1.z, x1.w};
#pragma unroll
                for (int j = 0; j < 8; j++) {
                    u64 xx = pk2(xv[j], xv[j]);
                    aIF[j] = fma2(wif, xx, aIF[j]);
                    aGO[j] = fma2(wgo, xx, aGO[j]);
                }
            }
            // elementwise: all 4 gates live in this thread
            float hbuf[8];
#pragma unroll
            for (int j = 0; j < 8; j++) {
                float zi, zf, zg, zo;
                upk2(aIF[j], zi, zf);
                upk2(aGO[j], zg, zo);
                float cc = sigm(zf) * cst[j] + sigm(zi) * ftanh(zg);
                cst[j] = cc;
                hbuf[j] = sigm(zo) * ftanh(cc);
            }
            *(float4*)&sm->xB[INX + uA][gA * 8]     = make_float4(hbuf[0], hbuf[1], hbuf[2], hbuf[3]);
            *(float4*)&sm->xB[INX + uA][gA * 8 + 4] = make_float4(hbuf[4], hbuf[5], hbuf[6], hbuf[7]);
        } else {
            // prefetch eps(s) and noise(s+1) into registers (consumed at stage 4)
            int gbe = b0 + beD;
            epsv = g_eps[((size_t)gbe * NSTEPS + s) * SD + dD];
            if (s + 1 < NSTEPS)
                nz = *(const float2*)&g_noise[((size_t)gbe * NSTEPS + (s + 1)) * ND + 2 * dD];
        }
        __syncthreads();   // h(s) ready

        // ===== stage 2: Phase B (warps 8-15) | zH part 1 (warps 0-7) =====
        if (tid >= 256) {
            u64 acc[8];
            {
                float2 bb = sm->b1p[oB];
                u64 bv = pk2(bb.x, bb.y);
#pragma unroll
                for (int j = 0; j < 8; j++) acc[j] = bv;
            }
#pragma unroll 4
            for (int k = 0; k < HH; k++) {
                float2 w = sm->w1p[k][oB];
                u64 wmv = pk2(w.x, w.y);
                float4 h0 = *(const float4*)&sm->xB[INX + k][gB * 8];
                float4 h1 = *(const float4*)&sm->xB[INX + k][gB * 8 + 4];
                float hv[8] = {h0.x, h0.y, h0.z, h0.w, h1.x, h1.y, h1.z, h1.w};
#pragma unroll
                for (int j = 0; j < 8; j++)
                    acc[j] = fma2(wmv, pk2(hv[j], hv[j]), acc[j]);
            }
#pragma unroll
            for (int j = 0; j < 8; j++) {
                float vm, vv; upk2(acc[j], vm, vv);
                sm->a1T[oB][gB * 8 + j] = make_float2(fmaxf(vm, 0.f), fmaxf(vv, 0.f));
            }
        } else {
            // restart accumulators for step s+1: bias + Wh·h(s), k = 24..55
#pragma unroll
            for (int j = 0; j < 8; j++) { aIF[j] = bifR; aGO[j] = bgoR; }
#pragma unroll 4
            for (int k = INX; k < INX + 32; k++) {
                float4 w = sm->wz4[k][uA];
                u64 wif = pk2(w.x, w.y), wgo = pk2(w.z, w.w);
                float4 x0 = *(const float4*)&sm->xB[k][gA * 8];
                float4 x1 = *(const float4*)&sm->xB[k][gA * 8 + 4];
                float xv[8] = {x0.x, x0.y, x0.z, x0.w, x1.x, x1.y, x1.z, x1.w};
#pragma unroll
                for (int j = 0; j < 8; j++) {
                    u64 xx = pk2(xv[j], xv[j]);
                    aIF[j] = fma2(wif, xx, aIF[j]);
                    aGO[j] = fma2(wgo, xx, aGO[j]);
                }
            }
        }
        __syncthreads();   // a1 ready

        // ===== stage 3: Phase C (warps 8-15) | zH part 2 (warps 0-7) =====
        if (tid >= 256) {
            u64 acc[8];
            {
                float2 bb = sm->b2p[oB];
                u64 bv = pk2(bb.x, bb.y);
#pragma unroll
                for (int j = 0; j < 8; j++) acc[j] = bv;
            }
#pragma unroll 4
            for (int k = 0; k < HH; k++) {
                float2 w = sm->w2p[k][oB];
                u64 wmv = pk2(w.x, w.y);
                float4 x0 = *(const float4*)&sm->a1T[k][gB * 8];
                float4 x1 = *(const float4*)&sm->a1T[k][gB * 8 + 2];
                float4 x2 = *(const float4*)&sm->a1T[k][gB * 8 + 4];
                float4 x3 = *(const float4*)&sm->a1T[k][gB * 8 + 6];
                u64 xv[8] = {pk2(x0.x, x0.y), pk2(x0.z, x0.w),
                             pk2(x1.x, x1.y), pk2(x1.z, x1.w),
                             pk2(x2.x, x2.y), pk2(x2.z, x2.w),
                             pk2(x3.x, x3.y), pk2(x3.z, x3.w)};
#pragma unroll
                for (int j = 0; j < 8; j++)
                    acc[j] = fma2(wmv, xv[j], acc[j]);
            }
#pragma unroll
            for (int j = 0; j < 8; j++) {
                float vm, vv; upk2(acc[j], vm, vv);
                sm->a2T[oB][gB * 8 + j] = make_float2(fmaxf(vm, 0.f), fmaxf(vv, 0.f));
            }
        } else {
            // zH part 2: k = 56..87
#pragma unroll 4
            for (int k = INX + 32; k < KIN; k++) {
                float4 w = sm->wz4[k][uA];
                u64 wif = pk2(w.x, w.y), wgo = pk2(w.z, w.w);
                float4 x0 = *(const float4*)&sm->xB[k][gA * 8];
                float4 x1 = *(const float4*)&sm->xB[k][gA * 8 + 4];
                float xv[8] = {x0.x, x0.y, x0.z, x0.w, x1.x, x1.y, x1.z, x1.w};
#pragma unroll
                for (int j = 0; j < 8; j++) {
                    u64 xx = pk2(xv[j], xv[j]);
                    aIF[j] = fma2(wif, xx, aIF[j]);
                    aGO[j] = fma2(wgo, xx, aGO[j]);
                }
            }
        }
        __syncthreads();   // a2 ready

        // ===== stage 4: D+E (warps 8-15, one (belem, dim) per thread) =====
        if (tid >= 256) {
            float2 b3 = sm->b3p[dD];
            u64 am = pk2(b3.x, b3.y);
#pragma unroll 8
            for (int k = 0; k < HH; k++) {
                float2 w = sm->w3p[k][dD];
                u64 x = *(const u64*)&sm->a2T[k][beD];
                am = fma2(pk2(w.x, w.y), x, am);
            }
            float mu, lv; upk2(am, mu, lv);
            float x = fmaf(__expf(0.5f * lv), epsv, mu);
            cum += x;
            g_out[((size_t)(b0 + beD) * TT + (s + 1)) * SD + dD] = cum;
            sm->xB[dD][beD] = x;
            if (s + 1 < NSTEPS) {
                sm->xB[SD + 2 * dD][beD]     = nz.x;
                sm->xB[SD + 2 * dD + 1][beD] = nz.y;
            }
        }
        __syncthreads();   // x(s), noise(s+1) staged for next stage 1
    }
}

extern "C" void kernel_launch(void* const* d_in, const int* in_sizes, int n_in,
                              void* d_out, int out_size) {
    const float* noise = (const float*)d_in[0];
    const float* eps   = (const float*)d_in[1];
    const float* Wx    = (const float*)d_in[2];
    const float* Wh    = (const float*)d_in[3];
    const float* b     = (const float*)d_in[4];
    const float* Wm1   = (const float*)d_in[5];
    const float* bm1   = (const float*)d_in[6];
    const float* Wm2   = (const float*)d_in[7];
    const float* bm2   = (const float*)d_in[8];
    const float* Wm3   = (const float*)d_in[9];
    const float* bm3   = (const float*)d_in[10];
    const float* Wv1   = (const float*)d_in[11];
    const float* bv1   = (const float*)d_in[12];
    const float* Wv2   = (const float*)d_in[13];
    const float* bv2   = (const float*)d_in[14];
    const float* Wv3   = (const float*)d_in[15];
    const float* bv3   = (const float*)d_in[16];
    float* out = (float*)d_out;

    const int smem_bytes = (int)sizeof(Smem);
    cudaFuncSetAttribute(genlstm_kernel,
                         cudaFuncAttributeMaxDynamicSharedMemorySize, smem_bytes);

    genlstm_kernel<<<NBATCH / NB, NTHREADS, smem_bytes>>>(
        noise, eps, Wx, Wh, b,
        Wm1, bm1, Wm2, bm2, Wm3, bm3,
        Wv1, bv1, Wv2, bv2, Wv3, bv3,
        out);
}

// round 17
// speedup vs baseline: 1.0211x; 1.0211x over previous
#include <cuda_runtime.h>

#define NBATCH   4096
#define TT       256
#define NSTEPS   255
#define ND       16
#define SD       8
#define HH       64
#define INX      24    // SD + ND
#define KIN      88    // INX + HH
#define G4       256
#define NB       32    // batch rows per CTA
#define XPAD     36    // xB row stride (floats), 144B
#define A1Q      9     // a1q row stride in float4 (36 floats)
#define APAD     34    // a2T row stride (float2)
#define NTHREADS 512

typedef unsigned long long u64;

struct __align__(16) Smem {
    float4 wz4[KIN][HH];      // (wi,wf,wg,wo) per (k, unit)
    float2 w1p[HH][HH];       // (wmu, wvar)
    float2 w2p[HH][HH];
    float2 w3p[HH][SD];
    float4 bz4[HH];
    float2 b1p[HH];
    float2 b2p[HH];
    float2 b3p[SD];
    float  xB[KIN][XPAD];     // rows: 0..7 x, 8..23 noise, 24..87 h ; col = belem
    float4 a1q[2][HH][A1Q];   // [path][out_of_L1][belem-pairs packed]
    float2 a2T[HH][APAD];     // [out_of_L2][belem] = (mu, var)
};

// ---- packed f32x2 helpers ----
__device__ __forceinline__ u64 pk2(float a, float b) {
    u64 r; asm("mov.b64 %0, {%1, %2};" : "=l"(r) : "f"(a), "f"(b)); return r;
}
__device__ __forceinline__ u64 dup2(float a) {
    u64 r; asm("mov.b64 %0, {%1, %1};" : "=l"(r) : "f"(a)); return r;
}
__device__ __forceinline__ void upk2(u64 v, float& a, float& b) {
    asm("mov.b64 {%0, %1}, %2;" : "=f"(a), "=f"(b) : "l"(v));
}
__device__ __forceinline__ u64 fma2(u64 a, u64 b, u64 c) {
    u64 d; asm("fma.rn.f32x2 %0, %1, %2, %3;" : "=l"(d) : "l"(a), "l"(b), "l"(c)); return d;
}

__device__ __forceinline__ float sigm(float x) {
    return __fdividef(1.f, 1.f + __expf(-x));
}
__device__ __forceinline__ float ftanh(float x) {
    float a = fabsf(x);
    float e = __expf(2.f * a);
    float r = 1.f - __fdividef(2.f, e + 1.f);
    return copysignf(r, x);
}

// accumulate z rows [K0, K1) into acc[gate][pair]
template<int K0, int K1>
__device__ __forceinline__ void zacc(const Smem* sm, u64 (&acc)[4][4], int uA, int gA) {
#pragma unroll 8
    for (int k = K0; k < K1; k++) {
        float4 w = sm->wz4[k][uA];
        u64 wi = dup2(w.x), wf = dup2(w.y), wg = dup2(w.z), wo = dup2(w.w);
        float4 x0 = *(const float4*)&sm->xB[k][gA * 8];
        float4 x1 = *(const float4*)&sm->xB[k][gA * 8 + 4];
        u64 p0 = pk2(x0.x, x0.y), p1 = pk2(x0.z, x0.w);
        u64 p2 = pk2(x1.x, x1.y), p3 = pk2(x1.z, x1.w);
        acc[0][0] = fma2(wi, p0, acc[0][0]); acc[0][1] = fma2(wi, p1, acc[0][1]);
        acc[0][2] = fma2(wi, p2, acc[0][2]); acc[0][3] = fma2(wi, p3, acc[0][3]);
        acc[1][0] = fma2(wf, p0, acc[1][0]); acc[1][1] = fma2(wf, p1, acc[1][1]);
        acc[1][2] = fma2(wf, p2, acc[1][2]); acc[1][3] = fma2(wf, p3, acc[1][3]);
        acc[2][0] = fma2(wg, p0, acc[2][0]); acc[2][1] = fma2(wg, p1, acc[2][1]);
        acc[2][2] = fma2(wg, p2, acc[2][2]); acc[2][3] = fma2(wg, p3, acc[2][3]);
        acc[3][0] = fma2(wo, p0, acc[3][0]); acc[3][1] = fma2(wo, p1, acc[3][1]);
        acc[3][2] = fma2(wo, p2, acc[3][2]); acc[3][3] = fma2(wo, p3, acc[3][3]);
    }
}

__global__ __launch_bounds__(NTHREADS, 1)
void genlstm_kernel(
    const float* __restrict__ g_noise, const float* __restrict__ g_eps,
    const float* __restrict__ Wx, const float* __restrict__ Wh, const float* __restrict__ b_g,
    const float* __restrict__ Wm1, const float* __restrict__ bm1,
    const float* __restrict__ Wm2, const float* __restrict__ bm2,
    const float* __restrict__ Wm3, const float* __restrict__ bm3,
    const float* __restrict__ Wv1, const float* __restrict__ bv1,
    const float* __restrict__ Wv2, const float* __restrict__ bv2,
    const float* __restrict__ Wv3, const float* __restrict__ bv3,
    float* __restrict__ g_out)
{
    extern __shared__ float smraw[];
    Smem* sm = reinterpret_cast<Smem*>(smraw);
    const int tid = threadIdx.x;
    const int b0  = blockIdx.x * NB;

    // ================= one-time staging =================
    for (int i = tid; i < KIN * G4; i += NTHREADS) {
        int k = i >> 8, r = i & 255, uu = r >> 2, g = r & 3;
        float v = (k < INX) ? Wx[k * G4 + g * 64 + uu] : Wh[(k - INX) * G4 + g * 64 + uu];
        reinterpret_cast<float*>(sm->wz4)[k * 256 + uu * 4 + g] = v;
    }
    if (tid < HH) {
        sm->bz4[tid] = make_float4(b_g[tid], b_g[64 + tid], b_g[128 + tid], b_g[192 + tid]);
        sm->b1p[tid] = make_float2(bm1[tid], bv1[tid]);
        sm->b2p[tid] = make_float2(bm2[tid], bv2[tid]);
    }
    if (tid < SD) sm->b3p[tid] = make_float2(bm3[tid], bv3[tid]);
    for (int i = tid; i < HH * HH; i += NTHREADS) {
        int k = i >> 6, o = i & 63;
        sm->w1p[k][o] = make_float2(Wm1[i], Wv1[i]);
        sm->w2p[k][o] = make_float2(Wm2[i], Wv2[i]);
    }
    for (int i = tid; i < HH * SD; i += NTHREADS) {
        int k = i >> 3, d = i & 7;
        sm->w3p[k][d] = make_float2(Wm3[i], Wv3[i]);
    }
    for (int i = tid; i < KIN * XPAD; i += NTHREADS)
        reinterpret_cast<float*>(sm->xB)[i] = 0.f;
    __syncthreads();
    // stage noise(step 0)
    {
        int be = tid >> 4, nd = tid & 15;
        sm->xB[SD + nd][be] = g_noise[((size_t)(b0 + be) * NSTEPS) * ND + nd];
    }
    if (tid < 256) {   // out[:,0,:] = 0
        int be = tid >> 3, d = tid & 7;
        g_out[((size_t)(b0 + be) * TT) * SD + d] = 0.f;
    }
    __syncthreads();

    // ---- roles ----
    const int uA = tid & 63, gA = (tid >> 6) & 3;     // LSTM side (tid<256)
    const int g2 = tid - 256;                         // MLP side (tid>=256)
    const int oB = g2 & 63, gB = g2 >> 6;             // B/C
    const int dD = g2 & 7,  beD = g2 >> 3;            // D/E + prefetch

    // LSTM-side persistent state
    u64 acc[4][4];        // [gate i,f,g,o][belem pair]
    float cst[8];
    float cum = 0.f;      // MLP-side cumsum
    float4 bzR = make_float4(0.f, 0.f, 0.f, 0.f);
    if (tid < 256) {
        bzR = sm->bz4[uA];
#pragma unroll
        for (int j = 0; j < 8; j++) cst[j] = 0.f;
        // pre-loop: acc = bias + Wx_n . noise_0   (h_{-1}=0, x_0=0)
        u64 bi = dup2(bzR.x), bf = dup2(bzR.y), bg = dup2(bzR.z), bo = dup2(bzR.w);
#pragma unroll
        for (int p = 0; p < 4; p++) { acc[0][p] = bi; acc[1][p] = bf; acc[2][p] = bg; acc[3][p] = bo; }
        zacc<SD, INX>(sm, acc, uA, gA);
    }

    for (int s = 0; s < NSTEPS; s++) {
        float epsv = 0.f;
        float2 nz = make_float2(0.f, 0.f);

        // ===== s1: zX-x + elementwise (LSTM) | prefetch (MLP) =====
        if (tid < 256) {
            zacc<0, SD>(sm, acc, uA, gA);
            float hbuf[8];
#pragma unroll
            for (int p = 0; p < 4; p++) {
                float i0, i1, f0, f1, gg0, gg1, o0, o1;
                upk2(acc[0][p], i0, i1); upk2(acc[1][p], f0, f1);
                upk2(acc[2][p], gg0, gg1); upk2(acc[3][p], o0, o1);
                float c0 = sigm(f0) * cst[2 * p]     + sigm(i0) * ftanh(gg0);
                float c1 = sigm(f1) * cst[2 * p + 1] + sigm(i1) * ftanh(gg1);
                cst[2 * p] = c0; cst[2 * p + 1] = c1;
                hbuf[2 * p]     = sigm(o0) * ftanh(c0);
                hbuf[2 * p + 1] = sigm(o1) * ftanh(c1);
            }
            *(float4*)&sm->xB[INX + uA][gA * 8]     = make_float4(hbuf[0], hbuf[1], hbuf[2], hbuf[3]);
            *(float4*)&sm->xB[INX + uA][gA * 8 + 4] = make_float4(hbuf[4], hbuf[5], hbuf[6], hbuf[7]);
        } else {
            int gbe = b0 + beD;
            epsv = g_eps[((size_t)gbe * NSTEPS + s) * SD + dD];
            if (s + 1 < NSTEPS)
                nz = *(const float2*)&g_noise[((size_t)gbe * NSTEPS + (s + 1)) * ND + 2 * dD];
        }
        __syncthreads();   // h(s) ready

        // ===== s2: zH part1 for s+1 (LSTM) | Phase B + noise-store (MLP) =====
        if (tid < 256) {
            if (s + 1 < NSTEPS) {
                u64 bi = dup2(bzR.x), bf = dup2(bzR.y), bg = dup2(bzR.z), bo = dup2(bzR.w);
#pragma unroll
                for (int p = 0; p < 4; p++) { acc[0][p] = bi; acc[1][p] = bf; acc[2][p] = bg; acc[3][p] = bo; }
                zacc<INX, INX + 32>(sm, acc, uA, gA);
            }
        } else {
            u64 am[4], av[4];
            {
                float2 bb = sm->b1p[oB];
                u64 bm = dup2(bb.x), bv = dup2(bb.y);
#pragma unroll
                for (int p = 0; p < 4; p++) { am[p] = bm; av[p] = bv; }
            }
#pragma unroll 8
            for (int k = 0; k < HH; k++) {
                float2 w = sm->w1p[k][oB];
                u64 wm = dup2(w.x), wv = dup2(w.y);
                float4 h0 = *(const float4*)&sm->xB[INX + k][gB * 8];
                float4 h1 = *(const float4*)&sm->xB[INX + k][gB * 8 + 4];
                u64 p0 = pk2(h0.x, h0.y), p1 = pk2(h0.z, h0.w);
                u64 p2 = pk2(h1.x, h1.y), p3 = pk2(h1.z, h1.w);
                am[0] = fma2(wm, p0, am[0]); am[1] = fma2(wm, p1, am[1]);
                am[2] = fma2(wm, p2, am[2]); am[3] = fma2(wm, p3, am[3]);
                av[0] = fma2(wv, p0, av[0]); av[1] = fma2(wv, p1, av[1]);
                av[2] = fma2(wv, p2, av[2]); av[3] = fma2(wv, p3, av[3]);
            }
            // relu + packed stores (pairs)
            {
                float m0, m1, m2, m3, m4, m5, m6, m7;
                upk2(am[0], m0, m1); upk2(am[1], m2, m3);
                upk2(am[2], m4, m5); upk2(am[3], m6, m7);
                sm->a1q[0][oB][gB * 2] = make_float4(fmaxf(m0, 0.f), fmaxf(m1, 0.f),
                                                     fmaxf(m2, 0.f), fmaxf(m3, 0.f));
                sm->a1q[0][oB][gB * 2 + 1] = make_float4(fmaxf(m4, 0.f), fmaxf(m5, 0.f),
                                                         fmaxf(m6, 0.f), fmaxf(m7, 0.f));
                upk2(av[0], m0, m1); upk2(av[1], m2, m3);
                upk2(av[2], m4, m5); upk2(av[3], m6, m7);
                sm->a1q[1][oB][gB * 2] = make_float4(fmaxf(m0, 0.f), fmaxf(m1, 0.f),
                                                     fmaxf(m2, 0.f), fmaxf(m3, 0.f));
                sm->a1q[1][oB][gB * 2 + 1] = make_float4(fmaxf(m4, 0.f), fmaxf(m5, 0.f),
                                                         fmaxf(m6, 0.f), fmaxf(m7, 0.f));
            }
            // stage noise(s+1) for LSTM's s4
            if (s + 1 < NSTEPS) {
                sm->xB[SD + 2 * dD][beD]     = nz.x;
                sm->xB[SD + 2 * dD + 1][beD] = nz.y;
            }
        }
        __syncthreads();   // a1 + noise(s+1) ready

        // ===== s3: zH part2 (LSTM) | Phase C (MLP) =====
        if (tid < 256) {
            if (s + 1 < NSTEPS) zacc<INX + 32, KIN>(sm, acc, uA, gA);
        } else {
            u64 am[4], av[4];
            {
                float2 bb = sm->b2p[oB];
                u64 bm = dup2(bb.x), bv = dup2(bb.y);
#pragma unroll
                for (int p = 0; p < 4; p++) { am[p] = bm; av[p] = bv; }
            }
#pragma unroll 8
            for (int k = 0; k < HH; k++) {
                float2 w = sm->w2p[k][oB];
                u64 wm = dup2(w.x), wv = dup2(w.y);
                float4 q0 = sm->a1q[0][k][gB * 2];
                float4 q1 = sm->a1q[0][k][gB * 2 + 1];
                float4 r0 = sm->a1q[1][k][gB * 2];
                float4 r1 = sm->a1q[1][k][gB * 2 + 1];
                am[0] = fma2(wm, pk2(q0.x, q0.y), am[0]);
                am[1] = fma2(wm, pk2(q0.z, q0.w), am[1]);
                am[2] = fma2(wm, pk2(q1.x, q1.y), am[2]);
                am[3] = fma2(wm, pk2(q1.z, q1.w), am[3]);
                av[0] = fma2(wv, pk2(r0.x, r0.y), av[0]);
                av[1] = fma2(wv, pk2(r0.z, r0.w), av[1]);
                av[2] = fma2(wv, pk2(r1.x, r1.y), av[2]);
                av[3] = fma2(wv, pk2(r1.z, r1.w), av[3]);
            }
            // transpose to (mu,var) per belem, relu, store
#pragma unroll
            for (int p = 0; p < 4; p++) {
                float m0, m1, v0, v1;
                upk2(am[p], m0, m1); upk2(av[p], v0, v1);
                sm->a2T[oB][gB * 8 + 2 * p]     = make_float2(fmaxf(m0, 0.f), fmaxf(v0, 0.f));
                sm->a2T[oB][gB * 8 + 2 * p + 1] = make_float2(fmaxf(m1, 0.f), fmaxf(v1, 0.f));
            }
        }
        __syncthreads();   // a2 ready

        // ===== s4: z-noise for s+1 (LSTM) | Phase D+E (MLP) =====
        if (tid < 256) {
            if (s + 1 < NSTEPS) zacc<SD, INX>(sm, acc, uA, gA);
        } else {
            float2 b3 = sm->b3p[dD];
            u64 am = pk2(b3.x, b3.y);
#pragma unroll 8
            for (int k = 0; k < HH; k++) {
                float2 w = sm->w3p[k][dD];
                u64 x = *(const u64*)&sm->a2T[k][beD];
                am = fma2(pk2(w.x, w.y), x, am);
            }
            float mu, lv; upk2(am, mu, lv);
            float x = fmaf(__expf(0.5f * lv), epsv, mu);
            cum += x;
            g_out[((size_t)(b0 + beD) * TT + (s + 1)) * SD + dD] = cum;
            sm->xB[dD][beD] = x;    // x(s+1) for next s1
        }
        __syncthreads();   // x(s+1) staged; z-noise reads done
    }
}

extern "C" void kernel_launch(void* const* d_in, const int* in_sizes, int n_in,
                              void* d_out, int out_size) {
    const float* noise = (const float*)d_in[0];
    const float* eps   = (const float*)d_in[1];
    const float* Wx    = (const float*)d_in[2];
    const float* Wh    = (const float*)d_in[3];
    const float* b     = (const float*)d_in[4];
    const float* Wm1   = (const float*)d_in[5];
    const float* bm1   = (const float*)d_in[6];
    const float* Wm2   = (const float*)d_in[7];
    const float* bm2   = (const float*)d_in[8];
    const float* Wm3   = (const float*)d_in[9];
    const float* bm3   = (const float*)d_in[10];
    const float* Wv1   = (const float*)d_in[11];
    const float* bv1   = (const float*)d_in[12];
    const float* Wv2   = (const float*)d_in[13];
    const float* bv2   = (const float*)d_in[14];
    const float* Wv3   = (const float*)d_in[15];
    const float* bv3   = (const float*)d_in[16];
    float* out = (float*)d_out;

    const int smem_bytes = (int)sizeof(Smem);
    cudaFuncSetAttribute(genlstm_kernel,
                         cudaFuncAttributeMaxDynamicSharedMemorySize, smem_bytes);

    genlstm_kernel<<<NBATCH / NB, NTHREADS, smem_bytes>>>(
        noise, eps, Wx, Wh, b,
        Wm1, bm1, Wm2, bm2, Wm3, bm3,
        Wv1, bv1, Wv2, bv2, Wv3, bv3,
        out);
}